// round 14
// baseline (speedup 1.0000x reference)
#include <cuda_runtime.h>
#include <cstdint>

#define NMODELS 128
#define SZ      256
#define BATCH   4096
#define NT      256
#define TILE_O  64
#define CH      16          // samples staged per barrier round
#define HCH     8           // samples per compute pass (acc registers)

#define XPITCH  260
#define X_FLOATS    (CH * XPITCH)          // 4160 per buffer
#define PART_FLOATS (CH * TILE_O * 9)      // 9216 (stride 9: conflict-free)
#define SMEM_BYTES  ((2 * X_FLOATS + PART_FLOATS + 64) * 4)

__device__ int            g_count[NMODELS];
__device__ unsigned short g_bucket[NMODELS * BATCH];   // 1 MB

__device__ __forceinline__ uint32_t smem_u32(const void* p) {
    uint32_t a;
    asm("{ .reg .u64 t; cvta.to.shared.u64 t, %1; cvt.u32.u64 %0, t; }"
        : "=r"(a) : "l"(p));
    return a;
}
__device__ __forceinline__ void cp16(uint32_t dst, const void* src) {
    asm volatile("cp.async.cg.shared.global [%0], [%1], 16;"
                 :: "r"(dst), "l"(src));
}

// ---- prep: bucket all ids in one 1024-thread CTA (smem atomics) ----
__global__ void prep_kernel(const int* __restrict__ ids) {
    __shared__ int scnt[NMODELS];
    int t = threadIdx.x;
    if (t < NMODELS) scnt[t] = 0;
    __syncthreads();
    #pragma unroll
    for (int i = 0; i < BATCH / 1024; i++) {
        int b  = t + i * 1024;
        int id = __ldg(&ids[b]);
        int p  = atomicAdd(&scnt[id], 1);
        g_bucket[id * BATCH + p] = (unsigned short)b;
    }
    __syncthreads();
    if (t < NMODELS) g_count[t] = scnt[t];
}

__global__ void __launch_bounds__(NT, 2)
fused_kernel(const float* __restrict__ inp,
             const float* __restrict__ wlut,
             const float* __restrict__ blut,
             float* __restrict__ out)
{
    extern __shared__ float smem[];
    float* x0_s   = smem;                          // [CH][XPITCH] ping
    float* x1_s   = x0_s + X_FLOATS;               // pong
    float* part   = x1_s + X_FLOATS;               // [(s*64+o)*9 + kp]
    float* bias_s = part + PART_FLOATS;            // [64]

    const int t    = threadIdx.x;
    const int og   = t & 15;        // 4 outputs: og*4..+3
    const int ks   = t >> 4;        // k-slice: ks*16..+15
    const int lane = t & 31;
    const int kp   = ks >> 1;       // partial slot 0..7

    const int m    = blockIdx.x >> 2;
    const int tile = blockIdx.x & 3;

    const int cnt = __ldg(&g_count[m]);
    const unsigned short* bk = g_bucket + m * BATCH;

    // ---- this thread's W block into registers (16 x float4) ----
    float4 wreg[16];
    {
        const float* wp = wlut + (size_t)m * SZ * SZ + (size_t)(ks * 16) * SZ
                          + tile * TILE_O + og * 4;
        #pragma unroll
        for (int i = 0; i < 16; i++)
            wreg[i] = __ldg((const float4*)(wp + (size_t)i * SZ));
    }

    if (t < 16)
        ((float4*)bias_s)[t] = __ldg(&((const float4*)(blut + m * SZ + tile * TILE_O))[t]);

    __syncthreads();          // bias_s visible
    if (cnt == 0) return;

    // ---- async prefetch of CH rows: 4 cp16 per thread ----
    auto prefetch = [&](int s0, float* xbuf) {
        #pragma unroll
        for (int i = 0; i < 4; i++) {
            int k  = t + i * NT;                 // 0..1023
            int s  = k >> 6;
            int i4 = k & 63;
            int idx = min(s0 + s, cnt - 1);      // clamp; extras discarded
            int bs  = __ldg(&bk[idx]);
            const float4* src = (const float4*)(inp + (size_t)bs * SZ) + i4;
            cp16(smem_u32(&xbuf[s * XPITCH + i4 * 4]), src);
        }
        asm volatile("cp.async.commit_group;" ::: "memory");
    };

    prefetch(0, x0_s);

    for (int s0 = 0, c = 0; s0 < cnt; s0 += CH, c++) {
        float* xb = (c & 1) ? x1_s : x0_s;
        float* xn = (c & 1) ? x0_s : x1_s;

        asm volatile("cp.async.wait_group 0;" ::: "memory");
        __syncthreads();   // xb visible; orders prev final-reads vs part-writes

        if (s0 + CH < cnt) prefetch(s0 + CH, xn);   // overlap with compute

        // ---- two compute passes of HCH samples each (same acc registers) ----
        #pragma unroll
        for (int h = 0; h < 2; h++) {
            float4 acc[HCH];
            const float* xbase = &xb[(h * HCH) * XPITCH + ks * 16];
            #pragma unroll
            for (int s = 0; s < HCH; s++) {
                float4 x0 = *(const float4*)&xbase[s * XPITCH];
                float4 x1 = *(const float4*)&xbase[s * XPITCH + 4];
                float4 x2 = *(const float4*)&xbase[s * XPITCH + 8];
                float4 x3 = *(const float4*)&xbase[s * XPITCH + 12];
                float4 a;
                a.x = x0.x * wreg[0].x; a.y = x0.x * wreg[0].y;
                a.z = x0.x * wreg[0].z; a.w = x0.x * wreg[0].w;
                a.x = fmaf(x0.y, wreg[1].x, a.x); a.y = fmaf(x0.y, wreg[1].y, a.y);
                a.z = fmaf(x0.y, wreg[1].z, a.z); a.w = fmaf(x0.y, wreg[1].w, a.w);
                a.x = fmaf(x0.z, wreg[2].x, a.x); a.y = fmaf(x0.z, wreg[2].y, a.y);
                a.z = fmaf(x0.z, wreg[2].z, a.z); a.w = fmaf(x0.z, wreg[2].w, a.w);
                a.x = fmaf(x0.w, wreg[3].x, a.x); a.y = fmaf(x0.w, wreg[3].y, a.y);
                a.z = fmaf(x0.w, wreg[3].z, a.z); a.w = fmaf(x0.w, wreg[3].w, a.w);

                a.x = fmaf(x1.x, wreg[4].x, a.x); a.y = fmaf(x1.x, wreg[4].y, a.y);
                a.z = fmaf(x1.x, wreg[4].z, a.z); a.w = fmaf(x1.x, wreg[4].w, a.w);
                a.x = fmaf(x1.y, wreg[5].x, a.x); a.y = fmaf(x1.y, wreg[5].y, a.y);
                a.z = fmaf(x1.y, wreg[5].z, a.z); a.w = fmaf(x1.y, wreg[5].w, a.w);
                a.x = fmaf(x1.z, wreg[6].x, a.x); a.y = fmaf(x1.z, wreg[6].y, a.y);
                a.z = fmaf(x1.z, wreg[6].z, a.z); a.w = fmaf(x1.z, wreg[6].w, a.w);
                a.x = fmaf(x1.w, wreg[7].x, a.x); a.y = fmaf(x1.w, wreg[7].y, a.y);
                a.z = fmaf(x1.w, wreg[7].z, a.z); a.w = fmaf(x1.w, wreg[7].w, a.w);

                a.x = fmaf(x2.x, wreg[8].x, a.x); a.y = fmaf(x2.x, wreg[8].y, a.y);
                a.z = fmaf(x2.x, wreg[8].z, a.z); a.w = fmaf(x2.x, wreg[8].w, a.w);
                a.x = fmaf(x2.y, wreg[9].x, a.x); a.y = fmaf(x2.y, wreg[9].y, a.y);
                a.z = fmaf(x2.y, wreg[9].z, a.z); a.w = fmaf(x2.y, wreg[9].w, a.w);
                a.x = fmaf(x2.z, wreg[10].x, a.x); a.y = fmaf(x2.z, wreg[10].y, a.y);
                a.z = fmaf(x2.z, wreg[10].z, a.z); a.w = fmaf(x2.z, wreg[10].w, a.w);
                a.x = fmaf(x2.w, wreg[11].x, a.x); a.y = fmaf(x2.w, wreg[11].y, a.y);
                a.z = fmaf(x2.w, wreg[11].z, a.z); a.w = fmaf(x2.w, wreg[11].w, a.w);

                a.x = fmaf(x3.x, wreg[12].x, a.x); a.y = fmaf(x3.x, wreg[12].y, a.y);
                a.z = fmaf(x3.x, wreg[12].z, a.z); a.w = fmaf(x3.x, wreg[12].w, a.w);
                a.x = fmaf(x3.y, wreg[13].x, a.x); a.y = fmaf(x3.y, wreg[13].y, a.y);
                a.z = fmaf(x3.y, wreg[13].z, a.z); a.w = fmaf(x3.y, wreg[13].w, a.w);
                a.x = fmaf(x3.z, wreg[14].x, a.x); a.y = fmaf(x3.z, wreg[14].y, a.y);
                a.z = fmaf(x3.z, wreg[14].z, a.z); a.w = fmaf(x3.z, wreg[14].w, a.w);
                a.x = fmaf(x3.w, wreg[15].x, a.x); a.y = fmaf(x3.w, wreg[15].y, a.y);
                a.z = fmaf(x3.w, wreg[15].z, a.z); a.w = fmaf(x3.w, wreg[15].w, a.w);
                acc[s] = a;
            }

            // ---- reduce: shfl-combine ks pairs, write 8 partials (stride 9) ----
            #pragma unroll
            for (int s = 0; s < HCH; s++) {
                float vx = acc[s].x, vy = acc[s].y, vz = acc[s].z, vw = acc[s].w;
                vx += __shfl_down_sync(0xffffffffu, vx, 16);
                vy += __shfl_down_sync(0xffffffffu, vy, 16);
                vz += __shfl_down_sync(0xffffffffu, vz, 16);
                vw += __shfl_down_sync(0xffffffffu, vw, 16);
                if (lane < 16) {
                    int o  = og * 4;
                    int sp = h * HCH + s;
                    part[(sp * TILE_O + o + 0) * 9 + kp] = vx;
                    part[(sp * TILE_O + o + 1) * 9 + kp] = vy;
                    part[(sp * TILE_O + o + 2) * 9 + kp] = vz;
                    part[(sp * TILE_O + o + 3) * 9 + kp] = vw;
                }
            }
        }
        __syncthreads();

        // ---- final: 2 consecutive outputs per thread x 2 rounds, STG.64 ----
        #pragma unroll
        for (int i = 0; i < 2; i++) {
            int p0 = 2 * t + i * 2 * NT;  // 0..1022
            int s  = p0 >> 6;
            int o  = p0 & 63;
            if (s0 + s < cnt) {
                const float* pp = &part[(s * TILE_O + o) * 9];
                float sum0 = bias_s[o];
                float sum1 = bias_s[o + 1];
                #pragma unroll
                for (int g = 0; g < 8; g++) { sum0 += pp[g]; sum1 += pp[9 + g]; }
                int bs = __ldg(&bk[s0 + s]);
                *(float2*)(out + (size_t)bs * SZ + tile * TILE_O + o)
                    = make_float2(sum0, sum1);
            }
        }
        // no trailing barrier: next iteration's top sync orders part reuse
    }
}

extern "C" void kernel_launch(void* const* d_in, const int* in_sizes, int n_in,
                              void* d_out, int out_size) {
    const float* inp  = (const float*)d_in[0];
    const int*   ids  = (const int*)  d_in[1];
    const float* wlut = (const float*)d_in[2];
    const float* blut = (const float*)d_in[3];
    float* out = (float*)d_out;

    cudaFuncSetAttribute(fused_kernel,
                         cudaFuncAttributeMaxDynamicSharedMemorySize, SMEM_BYTES);

    prep_kernel<<<1, 1024>>>(ids);
    fused_kernel<<<NMODELS * 4, NT, SMEM_BYTES>>>(inp, wlut, blut, out);
}

// round 15
// speedup vs baseline: 1.2644x; 1.2644x over previous
#include <cuda_runtime.h>
#include <cstdint>

#define NMODELS 128
#define SZ      256
#define BATCH   4096
#define NT      256
#define TILE_O  64
#define CH      8
#define NWORK   (NMODELS * 4)
#define GRID    296            // 148 SMs x 2 CTAs

#define XPITCH  260
#define X_FLOATS    (CH * XPITCH)          // 2080 per buffer
#define PART_FLOATS (CH * TILE_O * 9)      // 4608
#define SMEM_BYTES  ((2 * X_FLOATS + PART_FLOATS + 64) * 4 + BATCH * 2 + 16)

__device__ int g_work;
__device__ int g_done;

__device__ __forceinline__ uint32_t smem_u32(const void* p) {
    uint32_t a;
    asm("{ .reg .u64 t; cvta.to.shared.u64 t, %1; cvt.u32.u64 %0, t; }"
        : "=r"(a) : "l"(p));
    return a;
}
__device__ __forceinline__ void cp16(uint32_t dst, const void* src) {
    asm volatile("cp.async.cg.shared.global [%0], [%1], 16;"
                 :: "r"(dst), "l"(src));
}

__global__ void __launch_bounds__(NT, 2)
fused_kernel(const float* __restrict__ inp,
             const int*   __restrict__ ids,
             const float* __restrict__ wlut,
             const float* __restrict__ blut,
             float* __restrict__ out)
{
    extern __shared__ float smem[];
    float* x0_s   = smem;                          // [CH][XPITCH] ping
    float* x1_s   = x0_s + X_FLOATS;               // pong
    float* part   = x1_s + X_FLOATS;               // [(s*64+o)*9 + kp]
    float* bias_s = part + PART_FLOATS;            // [64]
    unsigned short* bucket = (unsigned short*)(bias_s + 64);
    __shared__ int cnt_s;
    __shared__ int w_s;

    const int t    = threadIdx.x;
    const int og   = t & 15;        // 4 outputs: og*4..+3
    const int ks   = t >> 4;        // k-slice: ks*16..+15
    const int lane = t & 31;
    const int kp   = ks >> 1;       // partial slot 0..7

    for (;;) {
        if (t == 0) w_s = atomicAdd(&g_work, 1);
        __syncthreads();            // w_s visible; bucket/part safe to reuse
        const int w = w_s;
        if (w >= NWORK) break;

        const int m    = w >> 2;
        const int tile = w & 3;

        if (t == 0) cnt_s = 0;
        __syncthreads();

        // ---- scan agent_ids (int4 loads) -> smem bucket ----
        const int4* ids4 = (const int4*)ids;
        #pragma unroll
        for (int i = 0; i < BATCH / (4 * NT); i++) {
            int c  = t + i * NT;
            int4 v = __ldg(&ids4[c]);
            int b  = c * 4;
            if (v.x == m) bucket[atomicAdd(&cnt_s, 1)] = (unsigned short)(b);
            if (v.y == m) bucket[atomicAdd(&cnt_s, 1)] = (unsigned short)(b + 1);
            if (v.z == m) bucket[atomicAdd(&cnt_s, 1)] = (unsigned short)(b + 2);
            if (v.w == m) bucket[atomicAdd(&cnt_s, 1)] = (unsigned short)(b + 3);
        }

        // ---- this thread's W block into registers (16 x float4) ----
        float4 wreg[16];
        {
            const float* wp = wlut + (size_t)m * SZ * SZ + (size_t)(ks * 16) * SZ
                              + tile * TILE_O + og * 4;
            #pragma unroll
            for (int i = 0; i < 16; i++)
                wreg[i] = __ldg((const float4*)(wp + (size_t)i * SZ));
        }

        if (t < 16)
            ((float4*)bias_s)[t] =
                __ldg(&((const float4*)(blut + m * SZ + tile * TILE_O))[t]);

        __syncthreads();
        const int cnt = cnt_s;
        if (cnt == 0) continue;

        // ---- async prefetch of chunk s0: 1 cp16 per thread x 2 rounds ----
        auto prefetch = [&](int s0, float* xbuf) {
            #pragma unroll
            for (int i = 0; i < 2; i++) {
                int k  = t + i * NT;                 // 0..511
                int s  = k >> 6;
                int i4 = k & 63;
                int idx = min(s0 + s, cnt - 1);      // clamp; extras discarded
                const float4* src = (const float4*)(inp + (size_t)bucket[idx] * SZ) + i4;
                cp16(smem_u32(&xbuf[s * XPITCH + i4 * 4]), src);
            }
            asm volatile("cp.async.commit_group;" ::: "memory");
        };

        prefetch(0, x0_s);

        for (int s0 = 0, c = 0; s0 < cnt; s0 += CH, c++) {
            float* xb = (c & 1) ? x1_s : x0_s;
            float* xn = (c & 1) ? x0_s : x1_s;

            asm volatile("cp.async.wait_group 0;" ::: "memory");
            __syncthreads();   // xb visible; orders prev final-reads vs part-writes

            if (s0 + CH < cnt) prefetch(s0 + CH, xn);   // overlap with compute

            // ---- compute: W in regs, x from smem; 16 k x 4 outs x CH samples ----
            float4 acc[CH];
            const float* xbase = &xb[ks * 16];
            #pragma unroll
            for (int s = 0; s < CH; s++) {
                float4 x0 = *(const float4*)&xbase[s * XPITCH];
                float4 x1 = *(const float4*)&xbase[s * XPITCH + 4];
                float4 x2 = *(const float4*)&xbase[s * XPITCH + 8];
                float4 x3 = *(const float4*)&xbase[s * XPITCH + 12];
                float4 a;
                a.x = x0.x * wreg[0].x; a.y = x0.x * wreg[0].y;
                a.z = x0.x * wreg[0].z; a.w = x0.x * wreg[0].w;
                a.x = fmaf(x0.y, wreg[1].x, a.x); a.y = fmaf(x0.y, wreg[1].y, a.y);
                a.z = fmaf(x0.y, wreg[1].z, a.z); a.w = fmaf(x0.y, wreg[1].w, a.w);
                a.x = fmaf(x0.z, wreg[2].x, a.x); a.y = fmaf(x0.z, wreg[2].y, a.y);
                a.z = fmaf(x0.z, wreg[2].z, a.z); a.w = fmaf(x0.z, wreg[2].w, a.w);
                a.x = fmaf(x0.w, wreg[3].x, a.x); a.y = fmaf(x0.w, wreg[3].y, a.y);
                a.z = fmaf(x0.w, wreg[3].z, a.z); a.w = fmaf(x0.w, wreg[3].w, a.w);

                a.x = fmaf(x1.x, wreg[4].x, a.x); a.y = fmaf(x1.x, wreg[4].y, a.y);
                a.z = fmaf(x1.x, wreg[4].z, a.z); a.w = fmaf(x1.x, wreg[4].w, a.w);
                a.x = fmaf(x1.y, wreg[5].x, a.x); a.y = fmaf(x1.y, wreg[5].y, a.y);
                a.z = fmaf(x1.y, wreg[5].z, a.z); a.w = fmaf(x1.y, wreg[5].w, a.w);
                a.x = fmaf(x1.z, wreg[6].x, a.x); a.y = fmaf(x1.z, wreg[6].y, a.y);
                a.z = fmaf(x1.z, wreg[6].z, a.z); a.w = fmaf(x1.z, wreg[6].w, a.w);
                a.x = fmaf(x1.w, wreg[7].x, a.x); a.y = fmaf(x1.w, wreg[7].y, a.y);
                a.z = fmaf(x1.w, wreg[7].z, a.z); a.w = fmaf(x1.w, wreg[7].w, a.w);

                a.x = fmaf(x2.x, wreg[8].x, a.x); a.y = fmaf(x2.x, wreg[8].y, a.y);
                a.z = fmaf(x2.x, wreg[8].z, a.z); a.w = fmaf(x2.x, wreg[8].w, a.w);
                a.x = fmaf(x2.y, wreg[9].x, a.x); a.y = fmaf(x2.y, wreg[9].y, a.y);
                a.z = fmaf(x2.y, wreg[9].z, a.z); a.w = fmaf(x2.y, wreg[9].w, a.w);
                a.x = fmaf(x2.z, wreg[10].x, a.x); a.y = fmaf(x2.z, wreg[10].y, a.y);
                a.z = fmaf(x2.z, wreg[10].z, a.z); a.w = fmaf(x2.z, wreg[10].w, a.w);
                a.x = fmaf(x2.w, wreg[11].x, a.x); a.y = fmaf(x2.w, wreg[11].y, a.y);
                a.z = fmaf(x2.w, wreg[11].z, a.z); a.w = fmaf(x2.w, wreg[11].w, a.w);

                a.x = fmaf(x3.x, wreg[12].x, a.x); a.y = fmaf(x3.x, wreg[12].y, a.y);
                a.z = fmaf(x3.x, wreg[12].z, a.z); a.w = fmaf(x3.x, wreg[12].w, a.w);
                a.x = fmaf(x3.y, wreg[13].x, a.x); a.y = fmaf(x3.y, wreg[13].y, a.y);
                a.z = fmaf(x3.y, wreg[13].z, a.z); a.w = fmaf(x3.y, wreg[13].w, a.w);
                a.x = fmaf(x3.z, wreg[14].x, a.x); a.y = fmaf(x3.z, wreg[14].y, a.y);
                a.z = fmaf(x3.z, wreg[14].z, a.z); a.w = fmaf(x3.z, wreg[14].w, a.w);
                a.x = fmaf(x3.w, wreg[15].x, a.x); a.y = fmaf(x3.w, wreg[15].y, a.y);
                a.z = fmaf(x3.w, wreg[15].z, a.z); a.w = fmaf(x3.w, wreg[15].w, a.w);
                acc[s] = a;
            }

            // ---- reduce: shfl-combine ks pairs, write 8 partials (stride 9) ----
            #pragma unroll
            for (int s = 0; s < CH; s++) {
                float vx = acc[s].x, vy = acc[s].y, vz = acc[s].z, vw = acc[s].w;
                vx += __shfl_down_sync(0xffffffffu, vx, 16);
                vy += __shfl_down_sync(0xffffffffu, vy, 16);
                vz += __shfl_down_sync(0xffffffffu, vz, 16);
                vw += __shfl_down_sync(0xffffffffu, vw, 16);
                if (lane < 16) {
                    int o = og * 4;
                    part[(s * TILE_O + o + 0) * 9 + kp] = vx;
                    part[(s * TILE_O + o + 1) * 9 + kp] = vy;
                    part[(s * TILE_O + o + 2) * 9 + kp] = vz;
                    part[(s * TILE_O + o + 3) * 9 + kp] = vw;
                }
            }
            __syncthreads();

            // ---- final: 2 consecutive outputs per thread, STG.64 ----
            {
                int p0 = 2 * t;               // 0..510
                int s  = p0 >> 6;
                int o  = p0 & 63;
                if (s0 + s < cnt) {
                    const float* pp = &part[(s * TILE_O + o) * 9];
                    float sum0 = bias_s[o];
                    float sum1 = bias_s[o + 1];
                    #pragma unroll
                    for (int g = 0; g < 8; g++) { sum0 += pp[g]; sum1 += pp[9 + g]; }
                    *(float2*)(out + (size_t)bucket[s0 + s] * SZ + tile * TILE_O + o)
                        = make_float2(sum0, sum1);
                }
            }
            // no trailing barrier: next iteration's top sync orders part reuse
        }
    }

    // ---- self-resetting work counters (graph-replay safe) ----
    __syncthreads();
    if (t == 0) {
        if (atomicAdd(&g_done, 1) == GRID - 1) {
            g_work = 0;
            g_done = 0;
        }
    }
}

extern "C" void kernel_launch(void* const* d_in, const int* in_sizes, int n_in,
                              void* d_out, int out_size) {
    const float* inp  = (const float*)d_in[0];
    const int*   ids  = (const int*)  d_in[1];
    const float* wlut = (const float*)d_in[2];
    const float* blut = (const float*)d_in[3];
    float* out = (float*)d_out;

    cudaFuncSetAttribute(fused_kernel,
                         cudaFuncAttributeMaxDynamicSharedMemorySize, SMEM_BYTES);

    fused_kernel<<<GRID, NT, SMEM_BYTES>>>(inp, ids, wlut, blut, out);
}